// round 11
// baseline (speedup 1.0000x reference)
#include <cuda_runtime.h>
#include <cstdint>

#define NA  16
#define NR  32
#define TPB 128

struct CoefTab {
    float4 PQ[16][16];  // [rp][k]  = (p[2rp,k], p[2rp+1,k], q[2rp,k], q[2rp+1,k])
    float4 Cq[16][8];   // [rp][kk] = (c[2rp,2kk], c[2rp+1,2kk], c[2rp,2kk+1], c[2rp+1,2kk+1])
    float2 RC[16];      // (rc[2rp], rc[2rp+1])  exponent constants (log2e folded)
    float2 C0[16];      // (C[2rp][0], C[2rp+1][0])
};
__constant__ CoefTab gTab;     // read path: LDC/LDCU (uniform port, not LSU)
__device__  CoefTab gStage;    // written by prep kernel, copied to gTab

static __device__ __forceinline__ unsigned long long pack2(float lo, float hi) {
    unsigned long long r;
    asm("mov.b64 %0, {%1, %2};" : "=l"(r) : "f"(lo), "f"(hi));
    return r;
}
static __device__ __forceinline__ void unpack2(unsigned long long v, float& lo, float& hi) {
    asm("mov.b64 {%0, %1}, %2;" : "=f"(lo), "=f"(hi) : "l"(v));
}
static __device__ __forceinline__ unsigned long long fma2(
    unsigned long long a, unsigned long long b, unsigned long long c) {
    unsigned long long d;
    asm("fma.rn.f32x2 %0, %1, %2, %3;" : "=l"(d) : "l"(a), "l"(b), "l"(c));
    return d;
}
static __device__ __forceinline__ float ex2(float x) {
    float y;
    asm("ex2.approx.f32 %0, %1;" : "=f"(y) : "f"(x));
    return y;
}

// ---- prep kernel: 1 block, 256 threads, fills gStage ----
// Faithful to reference: idx = r*A + k; (sigma, center) = FRB_W[idx], FRB_W[idx+1]
__global__ void prep_kernel(const float* __restrict__ frbw,
                            const float* __restrict__ C)
{
    const float L2E = 1.4426950408889634f;
    int i = threadIdx.x;
    {   // 256 PQ entries
        int rp = i >> 4, k = i & 15;
        int r0 = 2 * rp, r1 = 2 * rp + 1;
        float sig0 = frbw[r0 * NA + k], cen0 = frbw[r0 * NA + k + 1];
        float sig1 = frbw[r1 * NA + k], cen1 = frbw[r1 * NA + k + 1];
        float is0 = 1.0f / (sig0 * sig0);
        float is1 = 1.0f / (sig1 * sig1);
        gStage.PQ[rp][k] = make_float4(-0.5f * is0 * L2E, -0.5f * is1 * L2E,
                                        is0 * cen0 * L2E,  is1 * cen1 * L2E);
    }
    if (i < 128) {   // 128 Cq entries
        int rp = i >> 3, kk = i & 7;
        gStage.Cq[rp][kk] = make_float4(C[(2 * rp)     * (NA + 1) + 2 * kk + 1],
                                        C[(2 * rp + 1) * (NA + 1) + 2 * kk + 1],
                                        C[(2 * rp)     * (NA + 1) + 2 * kk + 2],
                                        C[(2 * rp + 1) * (NA + 1) + 2 * kk + 2]);
    }
    if (i < NR) {    // per-rule exponent constant and bias
        int r = i;
        float acc = 0.0f;
        for (int k = 0; k < NA; k++) {
            float sig = frbw[r * NA + k], cen = frbw[r * NA + k + 1];
            float is = 1.0f / (sig * sig);
            acc += -0.5f * is * L2E * cen * cen;
        }
        ((float*)gStage.RC)[r] = acc;               // float2[16] == float[32]
        ((float*)gStage.C0)[r] = C[r * (NA + 1)];
    }
}

// ---- main kernel: thread = sample, all coefficients from constant bank ----
__global__ void __launch_bounds__(TPB, 4)
tsk_kernel(const float* __restrict__ input,
           float* __restrict__ out, int B)
{
    int t = blockIdx.x * TPB + threadIdx.x;
    int tt = (t < B) ? t : (B - 1);

    // x row: 4 coalesced LDG.128, held as (x,x) dup pairs (32 regs)
    const float4* xr = (const float4*)(input + (size_t)tt * NA);
    float4 v0 = xr[0], v1 = xr[1], v2 = xr[2], v3 = xr[3];
    unsigned long long Xd[NA];
    Xd[ 0] = pack2(v0.x, v0.x);  Xd[ 1] = pack2(v0.y, v0.y);
    Xd[ 2] = pack2(v0.z, v0.z);  Xd[ 3] = pack2(v0.w, v0.w);
    Xd[ 4] = pack2(v1.x, v1.x);  Xd[ 5] = pack2(v1.y, v1.y);
    Xd[ 6] = pack2(v1.z, v1.z);  Xd[ 7] = pack2(v1.w, v1.w);
    Xd[ 8] = pack2(v2.x, v2.x);  Xd[ 9] = pack2(v2.y, v2.y);
    Xd[10] = pack2(v2.z, v2.z);  Xd[11] = pack2(v2.w, v2.w);
    Xd[12] = pack2(v3.x, v3.x);  Xd[13] = pack2(v3.y, v3.y);
    Xd[14] = pack2(v3.z, v3.z);  Xd[15] = pack2(v3.w, v3.w);

    float num = 0.0f, den = 0.0f;

    #pragma unroll 1      // body ~85 instrs: resident in L0 I$, uniform addresses
    for (int rp = 0; rp < 16; rp++) {
        float2 rc2 = gTab.RC[rp];
        float2 c02 = gTab.C0[rp];
        unsigned long long e  = pack2(rc2.x, rc2.y);   // (rule 2rp | rule 2rp+1)
        unsigned long long ch = pack2(c02.x, c02.y);
        const ulonglong2* pq = (const ulonglong2*)gTab.PQ[rp];  // (P|Q) per k
        const ulonglong2* cq = (const ulonglong2*)gTab.Cq[rp];  // (C_2kk|C_2kk+1)
        #pragma unroll
        for (int kk = 0; kk < 8; kk++) {
            ulonglong2 w0 = pq[2 * kk];       // P(k=2kk)   | Q(k=2kk)
            ulonglong2 w1 = pq[2 * kk + 1];   // P(k=2kk+1) | Q(k=2kk+1)
            ulonglong2 wc = cq[kk];           // C(k=2kk)   | C(k=2kk+1)
            unsigned long long xe = Xd[2 * kk], xo = Xd[2 * kk + 1];
            unsigned long long t0 = fma2(w0.x, xe, w0.y);
            unsigned long long t1 = fma2(w1.x, xo, w1.y);
            e  = fma2(t0, xe, e);
            ch = fma2(wc.x, xe, ch);
            e  = fma2(t1, xo, e);
            ch = fma2(wc.y, xo, ch);
        }
        float e0, e1, ch0, ch1;
        unpack2(e, e0, e1);
        unpack2(ch, ch0, ch1);
        float u0 = ex2(e0);
        float u1 = ex2(e1);
        num = fmaf(u0, ch0, num);
        num = fmaf(u1, ch1, num);
        den += u0 + u1;
    }

    if (t < B) out[t] = __fdividef(num, den);
}

extern "C" void kernel_launch(void* const* d_in, const int* in_sizes, int n_in,
                              void* d_out, int out_size)
{
    const float* input = (const float*)d_in[0];   // [B, 16] fp32
    const float* frbw  = (const float*)d_in[1];   // [1024]  fp32
    const float* Cm    = (const float*)d_in[2];   // [32,17] fp32
    float* out = (float*)d_out;                   // [B]     fp32

    int B = in_sizes[0] / NA;

    // 1) build packed tables on device
    prep_kernel<<<1, 256>>>(frbw, Cm);
    // 2) stage -> constant bank (device-to-device, graph-capturable)
    void* stage_ptr = nullptr;
    cudaGetSymbolAddress(&stage_ptr, gStage);
    cudaMemcpyToSymbolAsync(gTab, stage_ptr, sizeof(CoefTab), 0,
                            cudaMemcpyDeviceToDevice, 0);
    // 3) main kernel: 1 thread per sample
    int blocks = (B + TPB - 1) / TPB;             // 512 for B=65536
    tsk_kernel<<<blocks, TPB>>>(input, out, B);
}